// round 15
// baseline (speedup 1.0000x reference)
#include <cuda_runtime.h>
#include <cuda_bf16.h>

// Fixed problem shape: x[2, B, N] fp32, N=1024, B=32768.
#define NDIM 1024
#define THREADS 512
#define JPT 2            // output columns per thread (THREADS*JPT == NDIM)
#define RPI 4            // rows per pipeline stage (one "group")
#define STAGES 2
#define NBLOCKS 444      // 3 CTAs/SM x 148 SMs: fully-resident persistent grid

__device__ __forceinline__ void cp_async16(void* dst_smem, const void* src_gmem) {
    unsigned s = (unsigned)__cvta_generic_to_shared(dst_smem);
    asm volatile("cp.async.cg.shared.global [%0], [%1], 16;" :: "r"(s), "l"(src_gmem));
}
__device__ __forceinline__ void cp_commit()  { asm volatile("cp.async.commit_group;"); }
__device__ __forceinline__ void cp_wait0()   { asm volatile("cp.async.wait_group 0;" ::: "memory"); }

__global__ void __launch_bounds__(THREADS, 3)
mesh_kernel(const float* __restrict__ x, float* __restrict__ out,
            const float* __restrict__ diag, const float* __restrict__ off_diag,
            const int* __restrict__ pperm, const int* __restrict__ lperm,
            const int* __restrict__ rperm, int B) {
    // Split-plane staging, 2 stages of 4 rows each: 64 KB.
    __shared__ float sre[STAGES][RPI][NDIM];
    __shared__ float sim[STAGES][RPI][NDIM];

    const int t = threadIdx.x;
    const unsigned planes = (unsigned)B * NDIM;   // 33.5M: fits 32-bit
    const float* xr = x;
    const float* xi = x + planes;

    // Persistent strided schedule over 4-row groups.
    const int G       = (int)gridDim.x;
    const int b       = (int)blockIdx.x;
    const int ngroups = (B + RPI - 1) / RPI;
    const int mycount = (ngroups - b + G - 1) / G;      // 18 or 19 groups
    if (mycount <= 0) return;

    // Staging: thread covers rows {2*(t>>8), +1} of a stage, cols 4*(t&255).
    const int sv0 = (t >> 8) * 2;
    const int sc  = (t & 255) * 4;

    // ---- prologue: issue group 0 (one commit group) ----
    {
        int grow = b * RPI;
#pragma unroll
        for (int v = 0; v < 2; v++) {
            int row = min(grow + sv0 + v, B - 1);
            unsigned off = (unsigned)row * NDIM + sc;
            cp_async16(&sre[0][sv0 + v][sc], xr + off);
            cp_async16(&sim[0][sv0 + v][sc], xi + off);
        }
        cp_commit();
    }

    // ---- per-thread fused tables, loaded ONCE per persistent block ----
    // Output column j: k=R[j], p=P[k]; sources x[:, L[k]], x[:, L[p]];
    // coefs (diag_r[k], diag_i[k], off_r[p], off_i[p]).
    // Indices packed: pk[u] = L[k] | (L[p] << 16).
    int    pk[JPT];
    float4 cf[JPT];
    {
        int2 kk = ((const int2*)rperm)[t];        // rperm[2t], rperm[2t+1]
        int karr[2] = {kk.x, kk.y};
#pragma unroll
        for (int u = 0; u < JPT; u++) {
            int k = karr[u];
            int p = pperm[k];
            pk[u] = lperm[k] | (lperm[p] << 16);
            cf[u] = make_float4(diag[k], diag[NDIM + k],
                                off_diag[p], off_diag[NDIM + p]);
        }
    }

    float2* or2 = (float2*)out;
    float2* oi2 = (float2*)(out + planes);

    for (int i = 0; i < mycount; i++) {
        // Exactly one group pending: the one filling buffer i&1, issued a full
        // stage of compute ago. wait_group 0 also makes the drain trivial.
        cp_wait0();
        __syncthreads();   // copies visible; all threads left iter i-1

        // Issue stage i+1 AFTER the barrier: readers of buffer (i+1)&1
        // (iter i-1) are provably done. Copies overlap this stage's compute.
        if (i + 1 < mycount) {
            int grow = (b + (i + 1) * G) * RPI;
            int nb = (i + 1) & 1;
#pragma unroll
            for (int v = 0; v < 2; v++) {
                int row = min(grow + sv0 + v, B - 1);
                unsigned off = (unsigned)row * NDIM + sc;
                cp_async16(&sre[nb][sv0 + v][sc], xr + off);
                cp_async16(&sim[nb][sv0 + v][sc], xi + off);
            }
            cp_commit();
        }

        const float (*rr)[NDIM] = sre[i & 1];
        const float (*mm)[NDIM] = sim[i & 1];
        const int grow = (b + i * G) * RPI;
#pragma unroll
        for (int v = 0; v < RPI; v++) {
            int row = grow + v;
            if (row >= B) break;               // uniform per block
            const float* r_ = rr[v];
            const float* m_ = mm[v];
            float2 outR, outI;
            float* pR = &outR.x;
            float* pI = &outI.x;
#pragma unroll
            for (int u = 0; u < JPT; u++) {
                int iA = pk[u] & 0xFFFF;
                int iB = pk[u] >> 16;
                float aR = r_[iA], aI = m_[iA];   // col L[k]
                float bR = r_[iB], bI = m_[iB];   // col L[p]
                float4 c = cf[u];
                pR[u] = aR * c.x - aI * c.y + bR * c.z - bI * c.w;
                pI[u] = aR * c.y + aI * c.x + bR * c.w + bI * c.z;
            }
            unsigned ob = (unsigned)row * (NDIM / 2) + t;
            or2[ob] = outR;                    // STG.64, fully coalesced
            oi2[ob] = outI;
        }
    }
}

extern "C" void kernel_launch(void* const* d_in, const int* in_sizes, int n_in,
                              void* d_out, int out_size) {
    const float* x        = (const float*)d_in[0];   // [2, B, N] fp32
    const float* diag     = (const float*)d_in[1];   // [2, N]
    const float* off_diag = (const float*)d_in[2];   // [2, N]
    const int*   pperm    = (const int*)d_in[3];     // [N]
    const int*   lperm    = (const int*)d_in[4];     // [N]
    const int*   rperm    = (const int*)d_in[5];     // [N]
    float* out = (float*)d_out;

    const int n = in_sizes[1] / 2;                   // N (== NDIM)
    const int B = in_sizes[0] / (2 * n);

    int ngroups = (B + RPI - 1) / RPI;
    int grid = ngroups < NBLOCKS ? ngroups : NBLOCKS;
    mesh_kernel<<<grid, THREADS>>>(x, out, diag, off_diag,
                                   pperm, lperm, rperm, B);
}

// round 16
// speedup vs baseline: 1.1088x; 1.1088x over previous
#include <cuda_runtime.h>
#include <cuda_bf16.h>

// Fixed problem shape: x[2, B, N] fp32, N=1024, B=32768.
#define NDIM 1024
#define THREADS 512
#define JPT 2            // output columns per thread (THREADS*JPT == NDIM)
#define RPI 4            // rows staged per pipeline stage
#define ROWS 32          // batch rows per block
#define ITERS (ROWS / RPI)
#define STAGES 2

__device__ __forceinline__ void cp_async16(void* dst_smem, const void* src_gmem) {
    unsigned s = (unsigned)__cvta_generic_to_shared(dst_smem);
    asm volatile("cp.async.cg.shared.global [%0], [%1], 16;" :: "r"(s), "l"(src_gmem));
}
__device__ __forceinline__ void cp_commit()  { asm volatile("cp.async.commit_group;"); }
__device__ __forceinline__ void cp_wait0()   { asm volatile("cp.async.wait_group 0;" ::: "memory"); }
__device__ __forceinline__ void l2_prefetch(const void* p) {
    asm volatile("prefetch.global.L2 [%0];" :: "l"(p));
}

__global__ void __launch_bounds__(THREADS, 3)
mesh_kernel(const float* __restrict__ x, float* __restrict__ out,
            const float* __restrict__ diag, const float* __restrict__ off_diag,
            const int* __restrict__ pperm, const int* __restrict__ lperm,
            const int* __restrict__ rperm, int B) {
    // Split-plane staging, 2 stages of 4 rows each: 64 KB total.
    __shared__ float sre[STAGES][RPI][NDIM];
    __shared__ float sim[STAGES][RPI][NDIM];

    const int t = threadIdx.x;
    const unsigned planes = (unsigned)B * NDIM;   // 33.5M: fits 32-bit
    const float* xr = x;
    const float* xi = x + planes;

    const int row0 = (int)blockIdx.x * ROWS;
    // Staging: thread covers rows {2*(t>>8), +1} of the stage, cols 4*(t&255).
    const int sv0 = (t >> 8) * 2;
    const int sc  = (t & 255) * 4;

    // ---- prologue: issue stage 0 (one commit group) ----
#pragma unroll
    for (int v = 0; v < 2; v++) {
        int row = min(row0 + sv0 + v, B - 1);
        unsigned off = (unsigned)row * NDIM + sc;
        cp_async16(&sre[0][sv0 + v][sc], xr + off);
        cp_async16(&sim[0][sv0 + v][sc], xi + off);
    }
    cp_commit();

    // ---- per-thread fused tables (overlap the prologue copies) ----
    // Output column j: k=R[j], p=P[k]; sources x[:, L[k]], x[:, L[p]];
    // coefs (diag_r[k], diag_i[k], off_r[p], off_i[p]).
    // Indices packed as BYTE offsets: pk[u] = (4*L[k]) | ((4*L[p]) << 16).
    int    pk[JPT];
    float4 cf[JPT];
    {
        int2 kk = ((const int2*)rperm)[t];        // rperm[2t], rperm[2t+1]
        int karr[2] = {kk.x, kk.y};
#pragma unroll
        for (int u = 0; u < JPT; u++) {
            int k = karr[u];
            int p = pperm[k];
            pk[u] = (lperm[k] << 2) | (lperm[p] << 18);
            cf[u] = make_float4(diag[k], diag[NDIM + k],
                                off_diag[p], off_diag[NDIM + p]);
        }
    }

    float2* or2 = (float2*)out;
    float2* oi2 = (float2*)(out + planes);

    for (int it = 0; it < ITERS; it++) {
        // Exactly one group pending (buffer it&1, issued a full stage ago).
        cp_wait0();
        __syncthreads();   // copies visible to all; all threads left iter it-1

        // Issue stage it+1 AFTER the barrier: readers of buffer (it+1)&1
        // (iter it-1) are provably done. Copies overlap this stage's compute,
        // and (thanks to last iter's prefetch) mostly hit L2.
        if (it + 1 < ITERS) {
            int rb = row0 + (it + 1) * RPI + sv0;
            int nb = (it + 1) & 1;
#pragma unroll
            for (int v = 0; v < 2; v++) {
                int row = min(rb + v, B - 1);
                unsigned off = (unsigned)row * NDIM + sc;
                cp_async16(&sre[nb][sv0 + v][sc], xr + off);
                cp_async16(&sim[nb][sv0 + v][sc], xi + off);
            }
            cp_commit();
        }

        // L2 read-ahead for stage it+2 (one thread per 128B line: 8 threads
        // share a line; thread t covers cols sc..sc+3). Smooths DRAM reads
        // into the compute phase; next iter's cp.async then hits L2.
        if ((t & 7) == 0 && it + 2 < ITERS) {
            int rb = row0 + (it + 2) * RPI + sv0;
#pragma unroll
            for (int v = 0; v < 2; v++) {
                unsigned off = (unsigned)(rb + v) * NDIM + sc;
                l2_prefetch(xr + off);
                l2_prefetch(xi + off);
            }
        }

        const float (*rr)[NDIM] = sre[it & 1];
        const float (*mm)[NDIM] = sim[it & 1];
#pragma unroll
        for (int v = 0; v < RPI; v++) {
            int row = row0 + it * RPI + v;
            if (row >= B) break;               // uniform; full tiles for B=32768
            const char* r_ = (const char*)&rr[v][0];
            const char* m_ = (const char*)&mm[v][0];
            float2 outR, outI;
            float* pR = &outR.x;
            float* pI = &outI.x;
#pragma unroll
            for (int u = 0; u < JPT; u++) {
                int oA = pk[u] & 0xFFFF;           // byte offset of col L[k]
                int oB = ((unsigned)pk[u]) >> 16;  // byte offset of col L[p]
                float aR = *(const float*)(r_ + oA);
                float aI = *(const float*)(m_ + oA);
                float bR = *(const float*)(r_ + oB);
                float bI = *(const float*)(m_ + oB);
                float4 c = cf[u];
                pR[u] = aR * c.x - aI * c.y + bR * c.z - bI * c.w;
                pI[u] = aR * c.y + aI * c.x + bR * c.w + bI * c.z;
            }
            unsigned ob = (unsigned)row * (NDIM / 2) + t;
            or2[ob] = outR;                    // STG.64, fully coalesced
            oi2[ob] = outI;
        }
    }
}

extern "C" void kernel_launch(void* const* d_in, const int* in_sizes, int n_in,
                              void* d_out, int out_size) {
    const float* x        = (const float*)d_in[0];   // [2, B, N] fp32
    const float* diag     = (const float*)d_in[1];   // [2, N]
    const float* off_diag = (const float*)d_in[2];   // [2, N]
    const int*   pperm    = (const int*)d_in[3];     // [N]
    const int*   lperm    = (const int*)d_in[4];     // [N]
    const int*   rperm    = (const int*)d_in[5];     // [N]
    float* out = (float*)d_out;

    const int n = in_sizes[1] / 2;                   // N (== NDIM)
    const int B = in_sizes[0] / (2 * n);

    int grid = (B + ROWS - 1) / ROWS;
    mesh_kernel<<<grid, THREADS>>>(x, out, diag, off_diag,
                                   pperm, lperm, rperm, B);
}